// round 11
// baseline (speedup 1.0000x reference)
#include <cuda_runtime.h>
#include <cstdint>

// Problem constants (fixed by the reference)
constexpr int B  = 8;
constexpr int C  = 256;
constexpr int H  = 64;
constexpr int W  = 64;
constexpr int WC = 16;           // weight channels
constexpr int G  = C / WC;       // 16 groups sharing each weight
constexpr int HW = H * W;        // 4096
constexpr int Q  = HW / 4;       // float4 quads per plane = 1024
constexpr int GSTRIDE = WC * HW; // plane stride between groups (65536 floats)

constexpr int DEPTH = 3;         // cp.async pipeline stages

template <int N>
__device__ __forceinline__ void cp_wait() {
    asm volatile("cp.async.wait_group %0;" :: "n"(N));
}
__device__ __forceinline__ void cp_commit() {
    asm volatile("cp.async.commit_group;" ::: "memory");
}
// 16B async copy; src_size=0 zero-fills (used for out-of-image halo rows).
__device__ __forceinline__ void cpa16(uint32_t dst, const float* src, bool valid) {
    const int sz = valid ? 16 : 0;
    asm volatile("cp.async.ca.shared.global [%0], [%1], 16, %2;"
                 :: "r"(dst), "l"(src), "r"(sz) : "memory");
}

// One thread = one (b, wc, 2-row pair of quads) over all 16 groups.
//  - x rows stream through a per-thread 3-stage cp.async ring in smem
//    (3 groups of prefetch distance; latency fully covered; no barriers —
//    each thread consumes only its own copies via cp.async.wait_group).
//  - 18 weight float4s register-resident across all 16 groups.
//  - 64-thread CTAs, 8/SM: grid=1024 in ONE wave.
__global__ __launch_bounds__(64, 8) void agg_kernel_v8(
    const float* __restrict__ x,
    const float* __restrict__ w,
    float* __restrict__ out)
{
    __shared__ float4 sbuf[DEPTH][4][64];   // [stage][row][thread] = 12 KB

    const int tid  = threadIdx.x;
    const int idx  = blockIdx.x * 64 + tid; // 0 .. 65535
    const int q2   = idx & 511;             // 32 row-pairs x 16 quad-cols
    const int wc   = (idx >> 9) & (WC - 1);
    const int b    = idx >> 13;
    const int qcol = q2 & 15;
    const int oh   = (q2 >> 4) << 1;        // even output row
    const int p4   = oh * W + qcol * 4;     // first pixel of top quad

    const float mL = (qcol == 0)  ? 0.f : 1.f;
    const float mR = (qcol == 15) ? 0.f : 1.f;
    const bool ym  = (oh > 0);              // x row oh-1 exists
    const bool yp  = (oh < H - 2);          // x row oh+2 exists

    // Weights: 9 taps for output row oh (wv0) and row oh+1 (wv1).
    const float4* wp = (const float4*)(w + ((size_t)(b * WC + wc) * 9) * HW + p4);
    float4 wv0[9], wv1[9];
    #pragma unroll
    for (int t = 0; t < 9; t++) {
        wv0[t] = wp[(size_t)t * Q];
        wv1[t] = wp[(size_t)t * Q + 16];    // +64 floats = next row
    }

    const float* xc = x   + (size_t)(b * C + wc) * HW + p4;  // group-0 top quad
    float*       op = out + (size_t)(b * C + wc) * HW + p4;

    const uint32_t sb = (uint32_t)__cvta_generic_to_shared(&sbuf[0][0][tid]);

    // Issue the 4 row copies of one group into ring slot `slot`.
    auto issue = [&](int slot, const float* p) {
        const uint32_t d = sb + (uint32_t)(slot * 4) * 1024;
        cpa16(d,        ym ? p - W : p, ym);
        cpa16(d + 1024, p,              true);
        cpa16(d + 2048, p + W,          true);
        cpa16(d + 3072, yp ? p + 2 * W : p, yp);
        cp_commit();
    };

    // Prologue: fill the pipeline (stages 0..DEPTH-1 = groups 0..2).
    issue(0, xc);
    issue(1, xc + GSTRIDE);
    issue(2, xc + 2 * (size_t)GSTRIDE);
    xc += (size_t)DEPTH * GSTRIDE;

    const float4 z4 = make_float4(0.f, 0.f, 0.f, 0.f);

    #pragma unroll
    for (int g = 0; g < G; g++) {
        const int slot = g % DEPTH;

        // Wait until stage g has landed (<= pend groups still pending).
        const int pend = (G - 1 - g < DEPTH - 1) ? (G - 1 - g) : (DEPTH - 1);
        switch (pend) {
            case 0:  cp_wait<0>(); break;
            case 1:  cp_wait<1>(); break;
            default: cp_wait<2>(); break;
        }

        // Front-batch the 4 row reads (LDS.128, conflict-free).
        float4 c[4];
        c[0] = sbuf[slot][0][tid];
        c[1] = sbuf[slot][1][tid];
        c[2] = sbuf[slot][2][tid];
        c[3] = sbuf[slot][3][tid];

        // Refill this slot with group g+DEPTH (write lands long after the
        // LDS above have executed; single-thread ownership, no barrier).
        if (g + DEPTH < G) {
            issue(slot, xc);
            xc += GSTRIDE;
        }

        float4 acc0 = z4, acc1 = z4;

        #pragma unroll
        for (int a = 0; a < 4; a++) {
            const float4 cc = c[a];
            const float lf = __shfl_up_sync(0xffffffffu, cc.w, 1) * mL;
            const float rt = __shfl_down_sync(0xffffffffu, cc.x, 1) * mR;

            if (a < 3) {   // contributes to output row oh via tap row a
                const float4 wl = wv0[3 * a + 0];
                const float4 wm = wv0[3 * a + 1];
                const float4 wr = wv0[3 * a + 2];
                acc0.x += lf   * wl.x + cc.x * wm.x + cc.y * wr.x;
                acc0.y += cc.x * wl.y + cc.y * wm.y + cc.z * wr.y;
                acc0.z += cc.y * wl.z + cc.z * wm.z + cc.w * wr.z;
                acc0.w += cc.z * wl.w + cc.w * wm.w + rt   * wr.w;
            }
            if (a > 0) {   // contributes to output row oh+1 via tap row a-1
                const float4 wl = wv1[3 * (a - 1) + 0];
                const float4 wm = wv1[3 * (a - 1) + 1];
                const float4 wr = wv1[3 * (a - 1) + 2];
                acc1.x += lf   * wl.x + cc.x * wm.x + cc.y * wr.x;
                acc1.y += cc.x * wl.y + cc.y * wm.y + cc.z * wr.y;
                acc1.z += cc.y * wl.z + cc.z * wm.z + cc.w * wr.z;
                acc1.w += cc.z * wl.w + cc.w * wm.w + rt   * wr.w;
            }
        }

        *(float4*)(op)     = acc0;
        *(float4*)(op + W) = acc1;
        op += GSTRIDE;
    }
}

extern "C" void kernel_launch(void* const* d_in, const int* in_sizes, int n_in,
                              void* d_out, int out_size)
{
    const float* x = (const float*)d_in[0];   // (8,256,64,64) f32
    const float* w = (const float*)d_in[1];   // (8,16,9,4096) f32
    float* out = (float*)d_out;               // (8,256,64,64) f32

    const int total = B * WC * (Q / 2);       // 65536 threads (2 rows each)
    agg_kernel_v8<<<total / 64, 64>>>(x, w, out);
}